// round 1
// baseline (speedup 1.0000x reference)
#include <cuda_runtime.h>

// SlidingWindowAttention: B=2, H=16, L=4096, D=128, fp32
// causal + sliding window 2048 + 4 sink tokens.
// Round 0: fp32 flash-attention baseline (FMA-pipe bound by design; tensor
// cores come later once correctness + profile are established).

static constexpr int LSEQ  = 4096;
static constexpr int DIM   = 128;
static constexpr int WIN   = 2048;
static constexpr int NSINK = 4;
static constexpr int BQ    = 64;   // queries per block
static constexpr int BK    = 32;   // keys per shared tile

__global__ __launch_bounds__(256, 2)
void swa_fwd(const float* __restrict__ Qp, const float* __restrict__ Kp,
             const float* __restrict__ Vp, float* __restrict__ Op) {
    // Shared K/V tiles as float4 rows: [BK][32] float4 (= [BK][128] floats)
    __shared__ float4 Ks[BK * 32];
    __shared__ float4 Vs[BK * 32];

    const int bh   = blockIdx.y;
    const int q0   = blockIdx.x * BQ;
    const int tid  = threadIdx.x;
    const int lane = tid & 31;
    const int warp = tid >> 5;
    const int sub  = lane & 3;                 // which 32-dim slice (interleaved)
    const int qg   = q0 + warp * 8 + (lane >> 2);  // global query index

    const size_t base4 = (size_t)bh * LSEQ * (DIM / 4);
    const float4* Q4 = (const float4*)Qp + base4;
    const float4* K4 = (const float4*)Kp + base4;
    const float4* V4 = (const float4*)Vp + base4;
    float4*       O4 = (float4*)Op + base4;

    // Load this lane's slice of Q: dims { (i*4+sub)*4 .. +3 } for i=0..7
    float4 qr[8];
#pragma unroll
    for (int i = 0; i < 8; i++) qr[i] = Q4[(size_t)qg * 32 + i * 4 + sub];

    float4 acc[8];
#pragma unroll
    for (int i = 0; i < 8; i++) acc[i] = make_float4(0.f, 0.f, 0.f, 0.f);
    float m = -1e30f, l = 0.f;

    const float scale = 0.08838834764831845f;  // 1/sqrt(128)

    const int win_lo = q0 - (WIN - 1);
    const int t_lo   = (win_lo > 0) ? (win_lo / BK) : 0;
    const int t_hi   = (q0 + BQ - 1) / BK;

    // Process one key tile. sinkOnly: tile 0 when it is entirely left of every
    // query's window (then only k < NSINK contribute; causal is trivially true).
    auto process = [&](int kt0, bool sinkOnly) {
        __syncthreads();
#pragma unroll
        for (int r = 0; r < 4; r++) {
            int elem = tid + r * 256;          // 0..1023 float4 slots
            int j = elem >> 5, c = elem & 31;
            Ks[elem] = K4[(size_t)(kt0 + j) * 32 + c];
            Vs[elem] = V4[(size_t)(kt0 + j) * 32 + c];
        }
        __syncthreads();

#pragma unroll
        for (int jb = 0; jb < BK; jb += 16) {
            float s[16];
            float tmax = -1e30f;
#pragma unroll
            for (int j = 0; j < 16; j++) {
                const int jj = jb + j;
                float p = 0.f;
#pragma unroll
                for (int i = 0; i < 8; i++) {
                    float4 kx = Ks[jj * 32 + i * 4 + sub];
                    p = fmaf(qr[i].x, kx.x, p);
                    p = fmaf(qr[i].y, kx.y, p);
                    p = fmaf(qr[i].z, kx.z, p);
                    p = fmaf(qr[i].w, kx.w, p);
                }
                // reduce across the 4 lanes of this query's quad
                p += __shfl_xor_sync(0xffffffffu, p, 1);
                p += __shfl_xor_sync(0xffffffffu, p, 2);
                const int kg = kt0 + jj;
                const bool ok = sinkOnly
                    ? (kg < NSINK)
                    : ((kg <= qg) && ((kg + (WIN - 1) >= qg) || (kg < NSINK)));
                s[j] = ok ? p * scale : -1e30f;
                tmax = fmaxf(tmax, s[j]);
            }
            const float mnew = fmaxf(m, tmax);
            const float corr = __expf(m - mnew);
            l *= corr;
#pragma unroll
            for (int i = 0; i < 8; i++) {
                acc[i].x *= corr; acc[i].y *= corr;
                acc[i].z *= corr; acc[i].w *= corr;
            }
#pragma unroll
            for (int j = 0; j < 16; j++) {
                const float p = __expf(s[j] - mnew);
                l += p;
#pragma unroll
                for (int i = 0; i < 8; i++) {
                    float4 vx = Vs[(jb + j) * 32 + i * 4 + sub];
                    acc[i].x = fmaf(p, vx.x, acc[i].x);
                    acc[i].y = fmaf(p, vx.y, acc[i].y);
                    acc[i].z = fmaf(p, vx.z, acc[i].z);
                    acc[i].w = fmaf(p, vx.w, acc[i].w);
                }
            }
            m = mnew;
        }
    };

    if (t_lo > 0) process(0, true);            // sink-only tile
    for (int t = t_lo; t <= t_hi; ++t) process(t * BK, false);

    const float inv = 1.0f / l;
#pragma unroll
    for (int i = 0; i < 8; i++) {
        float4 o;
        o.x = acc[i].x * inv; o.y = acc[i].y * inv;
        o.z = acc[i].z * inv; o.w = acc[i].w * inv;
        O4[(size_t)qg * 32 + i * 4 + sub] = o;
    }
}

extern "C" void kernel_launch(void* const* d_in, const int* in_sizes, int n_in,
                              void* d_out, int out_size) {
    const float* q = (const float*)d_in[0];
    const float* k = (const float*)d_in[1];
    const float* v = (const float*)d_in[2];
    float*       o = (float*)d_out;

    const int BH = in_sizes[0] / (LSEQ * DIM);  // = B*H = 32
    dim3 grid(LSEQ / BQ, BH);
    swa_fwd<<<grid, 256>>>(q, k, v, o);
}

// round 2
// speedup vs baseline: 19.0789x; 19.0789x over previous
#include <cuda_runtime.h>
#include <cuda_fp16.h>
#include <cstdint>

// SlidingWindowAttention B=2,H=16,L=4096,D=128 fp32 io, window 2048, 4 sinks.
// R2: fp16 HMMA (mma.sync.m16n8k16) flash attention, fp32 accum.

static constexpr int LSEQ = 4096, DIM = 128, WIN = 2048, NSINK = 4;
static constexpr int BQ = 64, BK = 64, NBH = 32;
// softmax scale * log2(e), folded into Q fp16 conversion
static constexpr float SCALE2 = 0.08838834764831845f * 1.4426950408889634f;

__device__ __half g_Kh[(size_t)NBH * LSEQ * DIM];
__device__ __half g_Vh[(size_t)NBH * LSEQ * DIM];

__global__ void convert_kv(const float4* __restrict__ K4,
                           const float4* __restrict__ V4) {
    int i = blockIdx.x * blockDim.x + threadIdx.x;
    int n4 = NBH * LSEQ * DIM / 4;
    if (i >= n4) return;
    float4 a = K4[i], b = V4[i];
    __half2* kh = reinterpret_cast<__half2*>(g_Kh);
    __half2* vh = reinterpret_cast<__half2*>(g_Vh);
    kh[2 * i]     = __floats2half2_rn(a.x, a.y);
    kh[2 * i + 1] = __floats2half2_rn(a.z, a.w);
    vh[2 * i]     = __floats2half2_rn(b.x, b.y);
    vh[2 * i + 1] = __floats2half2_rn(b.z, b.w);
}

__device__ __forceinline__ float ex2(float x) {
    float y; asm("ex2.approx.ftz.f32 %0, %1;" : "=f"(y) : "f"(x)); return y;
}
__device__ __forceinline__ unsigned packh2(float lo, float hi) {
    unsigned r; asm("cvt.rn.f16x2.f32 %0, %1, %2;" : "=r"(r) : "f"(hi), "f"(lo));
    return r;
}
__device__ __forceinline__ void cpasync16(unsigned dst, const void* src) {
    asm volatile("cp.async.cg.shared.global [%0], [%1], 16;\n"
                 :: "r"(dst), "l"(src));
}
__device__ __forceinline__ void ldm_x4(unsigned addr, unsigned* r) {
    asm volatile("ldmatrix.sync.aligned.m8n8.x4.shared.b16 {%0,%1,%2,%3}, [%4];\n"
                 : "=r"(r[0]), "=r"(r[1]), "=r"(r[2]), "=r"(r[3]) : "r"(addr));
}
__device__ __forceinline__ void ldm_x4t(unsigned addr, unsigned* r) {
    asm volatile("ldmatrix.sync.aligned.m8n8.x4.trans.shared.b16 {%0,%1,%2,%3}, [%4];\n"
                 : "=r"(r[0]), "=r"(r[1]), "=r"(r[2]), "=r"(r[3]) : "r"(addr));
}
__device__ __forceinline__ void mma16816(float* d, const unsigned* a,
                                         unsigned b0, unsigned b1) {
    asm volatile(
        "mma.sync.aligned.m16n8k16.row.col.f32.f16.f16.f32 "
        "{%0,%1,%2,%3},{%4,%5,%6,%7},{%8,%9},{%0,%1,%2,%3};\n"
        : "+f"(d[0]), "+f"(d[1]), "+f"(d[2]), "+f"(d[3])
        : "r"(a[0]), "r"(a[1]), "r"(a[2]), "r"(a[3]), "r"(b0), "r"(b1));
}

// smem chunk addressing: 64 rows x 16 chunks of 16B per region; XOR swizzle.
__device__ __forceinline__ unsigned swoff(int row, int ch) {
    return (unsigned)((row << 8) + (((ch ^ (row & 7))) << 4));
}

__global__ void __launch_bounds__(128)
swa_hmma(const float* __restrict__ Q, float* __restrict__ O) {
    extern __shared__ char sm[];
    const unsigned sb = (unsigned)__cvta_generic_to_shared(sm);
    const int bh = blockIdx.y, q0 = blockIdx.x * BQ;
    const int tid = threadIdx.x, lane = tid & 31, warp = tid >> 5;
    const int gid = lane >> 2, tig = lane & 3;
    const int grp = lane >> 3, rr = lane & 7;

    const __half* Kg = g_Kh + (size_t)bh * LSEQ * DIM;
    const __half* Vg = g_Vh + (size_t)bh * LSEQ * DIM;

    const int wl = q0 - WIN + 1;
    const int t_lo = wl > 0 ? wl / BK : 0;
    const int t_hi = q0 / BK;
    const bool hasSink = t_lo > 0;
    const int nT = t_hi - t_lo + 1 + (hasSink ? 1 : 0);

    auto tileOf = [&](int s) -> int {
        if (s == 0) return t_hi;                 // diagonal first (validity)
        if (hasSink && s == nT - 1) return 0;    // sink tile last
        return t_lo + s - 1;
    };

    auto loadTile = [&](int kt0, int buf) {
        unsigned kb = sb + buf * 32768u, vb = kb + 16384u;
        const __half* kg = Kg + (size_t)kt0 * DIM;
        const __half* vg = Vg + (size_t)kt0 * DIM;
#pragma unroll
        for (int e = 0; e < 8; e++) {
            int idx = tid + e * 128;
            int row = idx >> 4, c = idx & 15;
            unsigned sw = swoff(row, c);
            cpasync16(kb + sw, kg + row * DIM + c * 8);
            cpasync16(vb + sw, vg + row * DIM + c * 8);
        }
        asm volatile("cp.async.commit_group;\n");
    };

    // prologue: first tile into buf0 (overlaps with Q staging below)
    loadTile(tileOf(0) * BK, 0);

    // stage Q (fp32 -> fp16 * SCALE2) into buf1 region, then grab fragments
    {
        const float* Qg0 = Q + ((size_t)bh * LSEQ + q0) * DIM;
#pragma unroll
        for (int e = 0; e < 8; e++) {
            int idx = tid + e * 128;
            int row = idx >> 4, c = idx & 15;
            const float4* s4 = (const float4*)(Qg0 + row * DIM + c * 8);
            float4 f0 = s4[0], f1 = s4[1];
            uint4 u;
            u.x = packh2(f0.x * SCALE2, f0.y * SCALE2);
            u.y = packh2(f0.z * SCALE2, f0.w * SCALE2);
            u.z = packh2(f1.x * SCALE2, f1.y * SCALE2);
            u.w = packh2(f1.z * SCALE2, f1.w * SCALE2);
            *(uint4*)(sm + 32768 + swoff(row, c)) = u;
        }
    }
    __syncthreads();
    unsigned qa[8][4];
#pragma unroll
    for (int kc = 0; kc < 8; kc++) {
        int row = warp * 16 + ((grp & 1) << 3) + rr;
        int ch = 2 * kc + (grp >> 1);
        ldm_x4(sb + 32768u + swoff(row, ch), qa[kc]);
    }
    __syncthreads();  // everyone done reading Q region before buf1 reuse

    float oc[16][4];
#pragma unroll
    for (int j = 0; j < 16; j++) oc[j][0] = oc[j][1] = oc[j][2] = oc[j][3] = 0.f;
    float m0 = -INFINITY, m1 = -INFINITY, l0 = 0.f, l1 = 0.f;

    for (int s = 0; s < nT; s++) {
        const bool more = (s + 1 < nT);
        if (more) {
            loadTile(tileOf(s + 1) * BK, (s + 1) & 1);
            asm volatile("cp.async.wait_group 1;\n" ::);
        } else {
            asm volatile("cp.async.wait_group 0;\n" ::);
        }
        __syncthreads();

        const int kt0 = tileOf(s) * BK;
        const unsigned kb = sb + (unsigned)(s & 1) * 32768u, vb = kb + 16384u;

        float sc[8][4];
#pragma unroll
        for (int j = 0; j < 8; j++) sc[j][0] = sc[j][1] = sc[j][2] = sc[j][3] = 0.f;

        // S = Q * K^T  (scores already in log2 domain via SCALE2 folding)
#pragma unroll
        for (int kc = 0; kc < 8; kc++) {
#pragma unroll
            for (int np = 0; np < 4; np++) {
                int row = np * 16 + ((grp >> 1) << 3) + rr;
                int ch = 2 * kc + (grp & 1);
                unsigned b[4];
                ldm_x4(kb + swoff(row, ch), b);
                mma16816(sc[2 * np], qa[kc], b[0], b[1]);
                mma16816(sc[2 * np + 1], qa[kc], b[2], b[3]);
            }
        }

        // mask (exact) on boundary tiles only
        const bool maskFree = (kt0 >= q0 + BQ - WIN) && (kt0 + BK - 1 <= q0);
        if (!maskFree) {
            const int qg0 = q0 + warp * 16 + gid, qg1 = qg0 + 8;
#pragma unroll
            for (int j = 0; j < 8; j++) {
                int kg = kt0 + j * 8 + 2 * tig;
                if (!(kg     <= qg0 && (kg     >= qg0 - WIN + 1 || kg     < NSINK))) sc[j][0] = -1e30f;
                if (!(kg + 1 <= qg0 && (kg + 1 >= qg0 - WIN + 1 || kg + 1 < NSINK))) sc[j][1] = -1e30f;
                if (!(kg     <= qg1 && (kg     >= qg1 - WIN + 1 || kg     < NSINK))) sc[j][2] = -1e30f;
                if (!(kg + 1 <= qg1 && (kg + 1 >= qg1 - WIN + 1 || kg + 1 < NSINK))) sc[j][3] = -1e30f;
            }
        }

        // online softmax (base-2)
        float mx0 = -INFINITY, mx1 = -INFINITY;
#pragma unroll
        for (int j = 0; j < 8; j++) {
            mx0 = fmaxf(mx0, fmaxf(sc[j][0], sc[j][1]));
            mx1 = fmaxf(mx1, fmaxf(sc[j][2], sc[j][3]));
        }
        mx0 = fmaxf(mx0, __shfl_xor_sync(0xffffffffu, mx0, 1));
        mx0 = fmaxf(mx0, __shfl_xor_sync(0xffffffffu, mx0, 2));
        mx1 = fmaxf(mx1, __shfl_xor_sync(0xffffffffu, mx1, 1));
        mx1 = fmaxf(mx1, __shfl_xor_sync(0xffffffffu, mx1, 2));
        const float m0n = fmaxf(m0, mx0), m1n = fmaxf(m1, mx1);
        const float c0 = ex2(m0 - m0n), c1 = ex2(m1 - m1n);
        l0 *= c0; l1 *= c1;
#pragma unroll
        for (int j = 0; j < 16; j++) {
            oc[j][0] *= c0; oc[j][1] *= c0; oc[j][2] *= c1; oc[j][3] *= c1;
        }
#pragma unroll
        for (int j = 0; j < 8; j++) {
            sc[j][0] = ex2(sc[j][0] - m0n); sc[j][1] = ex2(sc[j][1] - m0n);
            sc[j][2] = ex2(sc[j][2] - m1n); sc[j][3] = ex2(sc[j][3] - m1n);
            l0 += sc[j][0] + sc[j][1];
            l1 += sc[j][2] + sc[j][3];
        }
        m0 = m0n; m1 = m1n;

        // O += P * V
#pragma unroll
        for (int kc = 0; kc < 4; kc++) {
            unsigned pa[4];
            pa[0] = packh2(sc[2 * kc][0],     sc[2 * kc][1]);
            pa[1] = packh2(sc[2 * kc][2],     sc[2 * kc][3]);
            pa[2] = packh2(sc[2 * kc + 1][0], sc[2 * kc + 1][1]);
            pa[3] = packh2(sc[2 * kc + 1][2], sc[2 * kc + 1][3]);
#pragma unroll
            for (int dp = 0; dp < 8; dp++) {
                int row = kc * 16 + ((grp & 1) << 3) + rr;
                int ch = 2 * dp + (grp >> 1);
                unsigned v[4];
                ldm_x4t(vb + swoff(row, ch), v);
                mma16816(oc[2 * dp],     pa, v[0], v[1]);
                mma16816(oc[2 * dp + 1], pa, v[2], v[3]);
            }
        }
        __syncthreads();
    }

    // epilogue
    l0 += __shfl_xor_sync(0xffffffffu, l0, 1);
    l0 += __shfl_xor_sync(0xffffffffu, l0, 2);
    l1 += __shfl_xor_sync(0xffffffffu, l1, 1);
    l1 += __shfl_xor_sync(0xffffffffu, l1, 2);
    const float i0 = 1.f / l0, i1 = 1.f / l1;
    float* Og = O + ((size_t)bh * LSEQ + q0) * DIM;
    const int r0 = warp * 16 + gid, r1 = r0 + 8;
#pragma unroll
    for (int j = 0; j < 16; j++) {
        int d = j * 8 + 2 * tig;
        float2 w0 = {oc[j][0] * i0, oc[j][1] * i0};
        float2 w1 = {oc[j][2] * i1, oc[j][3] * i1};
        *(float2*)(Og + (size_t)r0 * DIM + d) = w0;
        *(float2*)(Og + (size_t)r1 * DIM + d) = w1;
    }
}

extern "C" void kernel_launch(void* const* d_in, const int* in_sizes, int n_in,
                              void* d_out, int out_size) {
    const float* q = (const float*)d_in[0];
    const float* k = (const float*)d_in[1];
    const float* v = (const float*)d_in[2];
    float* o = (float*)d_out;

    int n4 = NBH * LSEQ * DIM / 4;
    convert_kv<<<(n4 + 255) / 256, 256>>>((const float4*)k, (const float4*)v);

    cudaFuncSetAttribute(swa_hmma, cudaFuncAttributeMaxDynamicSharedMemorySize,
                         65536);
    dim3 grid(LSEQ / BQ, NBH);
    swa_hmma<<<grid, 128, 65536>>>(q, o);
}